// round 14
// baseline (speedup 1.0000x reference)
#include <cuda_runtime.h>
#include <math.h>

typedef unsigned int u32;

#define NN 100000
#define D 256
#define DOUT 64
#define EMAX 3200000
#define SCAN_B 1024
#define NSCAN ((NN + SCAN_B - 1) / SCAN_B)

// ---------------- scratch (device globals; no allocation allowed) ----------
__device__ __align__(16) float g_h0[(size_t)NN * D];
__device__ __align__(16) float g_h1[(size_t)NN * D];
__device__ __align__(16) float g_w2[D * D];
__device__ float g_b2[D];
__device__ float g_sum[D], g_sumsq[D], g_a[D], g_bv[D];
__device__ int g_tick;
__device__ int g_cnt[NN], g_cur[NN];
__device__ int g_off[NN + 1];
__device__ int g_bsum[NSCAN], g_bpre[NSCAN];
__device__ int g_ecol[EMAX];
__device__ float g_eval[EMAX];

// ---------------- cp.async helpers ------------------------------------------
__device__ __forceinline__ void cp16(u32 s, const void* g) {
    asm volatile("cp.async.ca.shared.global [%0], [%1], 16;\n" :: "r"(s), "l"(g));
}
__device__ __forceinline__ void cp_commit() {
    asm volatile("cp.async.commit_group;\n");
}
__device__ __forceinline__ void cp_wait0() {
    asm volatile("cp.async.wait_group 0;\n");
}

// ---------------- zero scratch ----------------------------------------------
__global__ void k_zero() {
    int i = blockIdx.x * blockDim.x + threadIdx.x;
    if (i < NN) { g_cnt[i] = 0; g_cur[i] = 0; }
    if (i < D)  { g_sum[i] = 0.f; g_sumsq[i] = 0.f; }
    if (i == 0) g_tick = 0;
}

// ---------------- BatchNorm stats + last-block finalize ----------------------
__global__ void k_bnsumfin(const float* __restrict__ x,
                           const float* __restrict__ gamma,
                           const float* __restrict__ beta) {
    int c = threadIdx.x;
    int rows_per = (NN + gridDim.x - 1) / gridDim.x;
    int r0 = blockIdx.x * rows_per;
    int r1 = min(r0 + rows_per, NN);
    float s = 0.f, s2 = 0.f;
    for (int r = r0; r < r1; r++) {
        float v = x[(size_t)r * D + c];
        s += v; s2 += v * v;
    }
    atomicAdd(&g_sum[c], s);
    atomicAdd(&g_sumsq[c], s2);
    __threadfence();
    __shared__ int last;
    if (c == 0) last = (atomicAdd(&g_tick, 1) == (int)gridDim.x - 1);
    __syncthreads();
    if (last) {
        float mean = g_sum[c] * (1.f / NN);
        float var  = g_sumsq[c] * (1.f / NN) - mean * mean;
        float a = gamma[c] * rsqrtf(var + 1e-5f);
        g_a[c] = a;
        g_bv[c] = beta[c] - mean * a;
    }
}

// fused: blocks 0..255 -> w2[k][j] = a[k]*w_in[k][j]; block 256 -> b2
__global__ void k_prepwb(const float* __restrict__ w_in, const float* __restrict__ b_in) {
    int j = threadIdx.x;
    if (blockIdx.x < 256) {
        int k = blockIdx.x;
        g_w2[k * D + j] = g_a[k] * w_in[k * D + j];
    } else {
        float s = b_in[j];
        for (int k = 0; k < D; k++) s += g_bv[k] * w_in[k * D + j];
        g_b2[j] = s;
    }
}

// ---------------- CSR build --------------------------------------------------
__global__ void k_hist(const int* __restrict__ rows, int E) {
    int i = blockIdx.x * blockDim.x + threadIdx.x;
    if (i < E) atomicAdd(&g_cnt[rows[i]], 1);
}

__global__ void k_scan1() {
    __shared__ int s[SCAN_B];
    int t = threadIdx.x;
    int i = blockIdx.x * SCAN_B + t;
    int v = (i < NN) ? g_cnt[i] : 0;
    s[t] = v;
    __syncthreads();
    for (int o = 1; o < SCAN_B; o <<= 1) {
        int add = (t >= o) ? s[t - o] : 0;
        __syncthreads();
        s[t] += add;
        __syncthreads();
    }
    if (i < NN) g_off[i + 1] = s[t];
    if (t == SCAN_B - 1) g_bsum[blockIdx.x] = s[t];
}

__global__ void k_scan2(int nb) {
    if (threadIdx.x == 0) {
        int run = 0;
        for (int b = 0; b < nb; b++) { g_bpre[b] = run; run += g_bsum[b]; }
    }
}

__global__ void k_scan3() {
    int i = blockIdx.x * blockDim.x + threadIdx.x;
    if (i == 0) g_off[0] = 0;
    if (i < NN) g_off[i + 1] += g_bpre[i >> 10];
}

__global__ void k_scatter(const int* __restrict__ rows, const int* __restrict__ cols,
                          const float* __restrict__ vals, int E) {
    int i = blockIdx.x * blockDim.x + threadIdx.x;
    if (i >= E) return;
    int r = rows[i];
    int p = g_off[r] + atomicAdd(&g_cur[r], 1);
    g_ecol[p] = cols[i];
    g_eval[p] = vals[i];
}

// ---------------- SpMM (CSR gather, 64 threads/row, unroll-8, .cs edges) ----
__global__ void __launch_bounds__(256) k_spmm(const float* __restrict__ xin_f,
                                              float* __restrict__ yout_f) {
    const float4* __restrict__ xin = (const float4*)xin_f;
    float4* __restrict__ yout      = (float4*)yout_f;
    int r = blockIdx.x * 4 + (threadIdx.x >> 6);
    int lane = threadIdx.x & 63;
    int e = g_off[r], e1 = g_off[r + 1];
    float4 acc = make_float4(0.f, 0.f, 0.f, 0.f);
    for (; e + 8 <= e1; e += 8) {
        int c0 = __ldcs(&g_ecol[e]);     float v0 = __ldcs(&g_eval[e]);
        int c1 = __ldcs(&g_ecol[e + 1]); float v1 = __ldcs(&g_eval[e + 1]);
        int c2 = __ldcs(&g_ecol[e + 2]); float v2 = __ldcs(&g_eval[e + 2]);
        int c3 = __ldcs(&g_ecol[e + 3]); float v3 = __ldcs(&g_eval[e + 3]);
        int c4 = __ldcs(&g_ecol[e + 4]); float v4 = __ldcs(&g_eval[e + 4]);
        int c5 = __ldcs(&g_ecol[e + 5]); float v5 = __ldcs(&g_eval[e + 5]);
        int c6 = __ldcs(&g_ecol[e + 6]); float v6 = __ldcs(&g_eval[e + 6]);
        int c7 = __ldcs(&g_ecol[e + 7]); float v7 = __ldcs(&g_eval[e + 7]);
        float4 x0 = xin[(size_t)c0 * 64 + lane];
        float4 x1 = xin[(size_t)c1 * 64 + lane];
        float4 x2 = xin[(size_t)c2 * 64 + lane];
        float4 x3 = xin[(size_t)c3 * 64 + lane];
        float4 x4 = xin[(size_t)c4 * 64 + lane];
        float4 x5 = xin[(size_t)c5 * 64 + lane];
        float4 x6 = xin[(size_t)c6 * 64 + lane];
        float4 x7 = xin[(size_t)c7 * 64 + lane];
        acc.x = fmaf(v0, x0.x, acc.x); acc.y = fmaf(v0, x0.y, acc.y);
        acc.z = fmaf(v0, x0.z, acc.z); acc.w = fmaf(v0, x0.w, acc.w);
        acc.x = fmaf(v1, x1.x, acc.x); acc.y = fmaf(v1, x1.y, acc.y);
        acc.z = fmaf(v1, x1.z, acc.z); acc.w = fmaf(v1, x1.w, acc.w);
        acc.x = fmaf(v2, x2.x, acc.x); acc.y = fmaf(v2, x2.y, acc.y);
        acc.z = fmaf(v2, x2.z, acc.z); acc.w = fmaf(v2, x2.w, acc.w);
        acc.x = fmaf(v3, x3.x, acc.x); acc.y = fmaf(v3, x3.y, acc.y);
        acc.z = fmaf(v3, x3.z, acc.z); acc.w = fmaf(v3, x3.w, acc.w);
        acc.x = fmaf(v4, x4.x, acc.x); acc.y = fmaf(v4, x4.y, acc.y);
        acc.z = fmaf(v4, x4.z, acc.z); acc.w = fmaf(v4, x4.w, acc.w);
        acc.x = fmaf(v5, x5.x, acc.x); acc.y = fmaf(v5, x5.y, acc.y);
        acc.z = fmaf(v5, x5.z, acc.z); acc.w = fmaf(v5, x5.w, acc.w);
        acc.x = fmaf(v6, x6.x, acc.x); acc.y = fmaf(v6, x6.y, acc.y);
        acc.z = fmaf(v6, x6.z, acc.z); acc.w = fmaf(v6, x6.w, acc.w);
        acc.x = fmaf(v7, x7.x, acc.x); acc.y = fmaf(v7, x7.y, acc.y);
        acc.z = fmaf(v7, x7.z, acc.z); acc.w = fmaf(v7, x7.w, acc.w);
    }
    for (; e < e1; e++) {
        int c = __ldcs(&g_ecol[e]); float v = __ldcs(&g_eval[e]);
        float4 xv = xin[(size_t)c * 64 + lane];
        acc.x = fmaf(v, xv.x, acc.x); acc.y = fmaf(v, xv.y, acc.y);
        acc.z = fmaf(v, xv.z, acc.z); acc.w = fmaf(v, xv.w, acc.w);
    }
    yout[(size_t)r * 64 + lane] = acc;
}

// ------ fp32 GEMM 128x128, 8x8/thread, KTILE=16, cp.async B, dbl-buffered ---
template <bool TANH>
__global__ void __launch_bounds__(256, 2) k_gemm128(const float* __restrict__ A,
                                                    const float* __restrict__ B,
                                                    const float* __restrict__ bias,
                                                    float* __restrict__ C, int M) {
    __shared__ float As[2][16 * 132];   // transposed, padded: As[b][k*132 + m]
    __shared__ float Bs[2][16 * 128];   // natural: Bs[b][k*128 + n]
    const int tid = threadIdx.x;
    const int tx = tid & 15, ty = tid >> 4;
    const int bm = blockIdx.x * 128;
    const int bn = blockIdx.y * 128;

    float acc[8][8];
#pragma unroll
    for (int i = 0; i < 8; i++)
#pragma unroll
        for (int j = 0; j < 8; j++) acc[i][j] = 0.f;

    const int ar = tid >> 1, aq = (tid & 1) * 8;   // A: row, k-offset (2 float4)
    const int bk = tid >> 4, bc = (tid & 15) * 8;  // B: k-row, col (2 float4)
    const int gr = bm + ar;
    const bool avalid = (gr < M);
    const float* Arow = A + (size_t)gr * 256;
    const float* Bptr = B + (size_t)bk * 256 + bn + bc;

    u32 sB0 = (u32)__cvta_generic_to_shared(&Bs[0][bk * 128 + bc]);
    u32 sB1 = (u32)__cvta_generic_to_shared(&Bs[1][bk * 128 + bc]);

    // prologue: tile 0
    cp16(sB0, Bptr);
    cp16(sB0 + 16, Bptr + 4);
    cp_commit();
    {
        float4 a0 = make_float4(0.f, 0.f, 0.f, 0.f), a1 = a0;
        if (avalid) {
            a0 = *(const float4*)(Arow + aq);
            a1 = *(const float4*)(Arow + aq + 4);
        }
        As[0][(aq + 0) * 132 + ar] = a0.x;
        As[0][(aq + 1) * 132 + ar] = a0.y;
        As[0][(aq + 2) * 132 + ar] = a0.z;
        As[0][(aq + 3) * 132 + ar] = a0.w;
        As[0][(aq + 4) * 132 + ar] = a1.x;
        As[0][(aq + 5) * 132 + ar] = a1.y;
        As[0][(aq + 6) * 132 + ar] = a1.z;
        As[0][(aq + 7) * 132 + ar] = a1.w;
    }
    cp_wait0();
    __syncthreads();

    for (int k0 = 0; k0 < 256; k0 += 16) {
        const int buf = (k0 >> 4) & 1;
        const bool has_next = (k0 + 16) < 256;
        float4 a0n = make_float4(0.f, 0.f, 0.f, 0.f), a1n = a0n;
        if (has_next) {
            u32 sBn = buf ? sB0 : sB1;
            const float* Bn = Bptr + (size_t)(k0 + 16) * 256;
            cp16(sBn, Bn);
            cp16(sBn + 16, Bn + 4);
            cp_commit();
            if (avalid) {
                a0n = *(const float4*)(Arow + k0 + 16 + aq);
                a1n = *(const float4*)(Arow + k0 + 16 + aq + 4);
            }
        }
#pragma unroll
        for (int k = 0; k < 16; k++) {
            float4 x0 = *(const float4*)&As[buf][k * 132 + ty * 8];
            float4 x1 = *(const float4*)&As[buf][k * 132 + ty * 8 + 4];
            float4 y0 = *(const float4*)&Bs[buf][k * 128 + tx * 8];
            float4 y1 = *(const float4*)&Bs[buf][k * 128 + tx * 8 + 4];
            float aa[8] = {x0.x, x0.y, x0.z, x0.w, x1.x, x1.y, x1.z, x1.w};
            float bb[8] = {y0.x, y0.y, y0.z, y0.w, y1.x, y1.y, y1.z, y1.w};
#pragma unroll
            for (int i = 0; i < 8; i++)
#pragma unroll
                for (int j = 0; j < 8; j++)
                    acc[i][j] = fmaf(aa[i], bb[j], acc[i][j]);
        }
        if (has_next) {
            const int nb = buf ^ 1;
            As[nb][(aq + 0) * 132 + ar] = a0n.x;
            As[nb][(aq + 1) * 132 + ar] = a0n.y;
            As[nb][(aq + 2) * 132 + ar] = a0n.z;
            As[nb][(aq + 3) * 132 + ar] = a0n.w;
            As[nb][(aq + 4) * 132 + ar] = a1n.x;
            As[nb][(aq + 5) * 132 + ar] = a1n.y;
            As[nb][(aq + 6) * 132 + ar] = a1n.z;
            As[nb][(aq + 7) * 132 + ar] = a1n.w;
            cp_wait0();
            __syncthreads();
        }
    }

    float4 bl = *(const float4*)(bias + bn + tx * 8);
    float4 bh = *(const float4*)(bias + bn + tx * 8 + 4);
    float bb8[8] = {bl.x, bl.y, bl.z, bl.w, bh.x, bh.y, bh.z, bh.w};
#pragma unroll
    for (int i = 0; i < 8; i++) {
        int grr = bm + ty * 8 + i;
        if (grr >= M) continue;
        float o[8];
#pragma unroll
        for (int j = 0; j < 8; j++) {
            o[j] = acc[i][j] + bb8[j];
            if (TANH) o[j] = tanhf(o[j]);
        }
        *(float4*)(C + (size_t)grr * 256 + bn + tx * 8) =
            make_float4(o[0], o[1], o[2], o[3]);
        *(float4*)(C + (size_t)grr * 256 + bn + tx * 8 + 4) =
            make_float4(o[4], o[5], o[6], o[7]);
    }
}

// ---------------- fp32 GEMM 128x64 (N=64 logits) -----------------------------
template <bool TANH>
__global__ void __launch_bounds__(256) k_gemm(const float* __restrict__ A,
                                              const float* __restrict__ B,
                                              const float* __restrict__ bias,
                                              float* __restrict__ C,
                                              int M, int N) {
    __shared__ float As[16][128];
    __shared__ float Bs[16][64];
    const int tid = threadIdx.x;
    const int tx = tid & 15, ty = tid >> 4;
    const int bm = blockIdx.x * 128;
    const int bn = blockIdx.y * 64;
    float acc[8][4];
#pragma unroll
    for (int i = 0; i < 8; i++)
#pragma unroll
        for (int j = 0; j < 4; j++) acc[i][j] = 0.f;

    for (int k0 = 0; k0 < 256; k0 += 16) {
#pragma unroll
        for (int q = 0; q < 2; q++) {
            int idx = tid * 2 + q;
            int row = idx >> 2, cg = idx & 3;
            int gr = bm + row;
            float4 v = make_float4(0.f, 0.f, 0.f, 0.f);
            if (gr < M) v = *(const float4*)(A + (size_t)gr * 256 + k0 + cg * 4);
            As[cg * 4 + 0][row] = v.x;
            As[cg * 4 + 1][row] = v.y;
            As[cg * 4 + 2][row] = v.z;
            As[cg * 4 + 3][row] = v.w;
        }
        {
            int row = tid >> 4, c4 = tid & 15;
            *(float4*)&Bs[row][c4 * 4] =
                *(const float4*)(B + (size_t)(k0 + row) * N + bn + c4 * 4);
        }
        __syncthreads();
#pragma unroll
        for (int k = 0; k < 16; k++) {
            float4 a0 = *(const float4*)&As[k][ty * 8];
            float4 a1 = *(const float4*)&As[k][ty * 8 + 4];
            float4 b0 = *(const float4*)&Bs[k][tx * 4];
            float av[8] = {a0.x, a0.y, a0.z, a0.w, a1.x, a1.y, a1.z, a1.w};
            float bv4[4] = {b0.x, b0.y, b0.z, b0.w};
#pragma unroll
            for (int i = 0; i < 8; i++)
#pragma unroll
                for (int j = 0; j < 4; j++)
                    acc[i][j] = fmaf(av[i], bv4[j], acc[i][j]);
        }
        __syncthreads();
    }

    float4 bb = *(const float4*)(bias + bn + tx * 4);
#pragma unroll
    for (int i = 0; i < 8; i++) {
        int gr = bm + ty * 8 + i;
        if (gr < M) {
            float4 o;
            o.x = acc[i][0] + bb.x;
            o.y = acc[i][1] + bb.y;
            o.z = acc[i][2] + bb.z;
            o.w = acc[i][3] + bb.w;
            if (TANH) {
                o.x = tanhf(o.x); o.y = tanhf(o.y);
                o.z = tanhf(o.z); o.w = tanhf(o.w);
            }
            *(float4*)(C + (size_t)gr * N + bn + tx * 4) = o;
        }
    }
}

// ---------------- launch -----------------------------------------------------
extern "C" void kernel_launch(void* const* d_in, const int* in_sizes, int n_in,
                              void* d_out, int out_size) {
    const float* x      = (const float*)d_in[0];
    const int*   erows  = (const int*)d_in[1];
    const int*   ecols  = (const int*)d_in[2];
    const float* evals  = (const float*)d_in[3];
    const float* gamma  = (const float*)d_in[4];
    const float* beta   = (const float*)d_in[5];
    const float* w_in   = (const float*)d_in[6];
    const float* b_in   = (const float*)d_in[7];
    const float* w_conv = (const float*)d_in[8];
    const float* b_conv = (const float*)d_in[9];
    const float* w_out  = (const float*)d_in[10];
    const float* b_out  = (const float*)d_in[11];
    const int E = in_sizes[1];
    float* out = (float*)d_out;

    float *p_h0, *p_h1, *p_w2, *p_b2;
    cudaGetSymbolAddress((void**)&p_h0, g_h0);
    cudaGetSymbolAddress((void**)&p_h1, g_h1);
    cudaGetSymbolAddress((void**)&p_w2, g_w2);
    cudaGetSymbolAddress((void**)&p_b2, g_b2);

    static cudaStream_t s_csr = 0;
    static cudaEvent_t ev_fork = 0, ev_csr = 0;
    if (!s_csr) {
        cudaStreamCreateWithFlags(&s_csr, cudaStreamNonBlocking);
        cudaEventCreateWithFlags(&ev_fork, cudaEventDisableTiming);
        cudaEventCreateWithFlags(&ev_csr, cudaEventDisableTiming);
    }

    // main stream: zero everything, then fork
    k_zero<<<(NN + 255) / 256, 256>>>();
    cudaEventRecord(ev_fork, 0);
    cudaStreamWaitEvent(s_csr, ev_fork, 0);

    // branch B (side stream): CSR build — independent of BN/GEMM1
    k_hist<<<(E + 255) / 256, 256, 0, s_csr>>>(erows, E);
    k_scan1<<<NSCAN, SCAN_B, 0, s_csr>>>();
    k_scan2<<<1, 32, 0, s_csr>>>(NSCAN);
    k_scan3<<<(NN + 255) / 256, 256, 0, s_csr>>>();
    k_scatter<<<(E + 255) / 256, 256, 0, s_csr>>>(erows, ecols, evals, E);
    cudaEventRecord(ev_csr, s_csr);

    // branch A (main stream): BN stats -> folded weights -> GEMM1
    k_bnsumfin<<<512, 256>>>(x, gamma, beta);
    k_prepwb<<<257, 256>>>(w_in, b_in);
    dim3 g1((NN + 127) / 128, 2);
    k_gemm128<true><<<g1, 256>>>(x, p_w2, p_b2, p_h0, NN);

    // join: SpMM needs both h0 (A) and CSR (B)
    cudaStreamWaitEvent(0, ev_csr, 0);

    // 4 fp32 SpMM hops: h0 -> h1 -> h0 -> h1 -> h0
    k_spmm<<<NN / 4, 256>>>(p_h0, p_h1);
    k_spmm<<<NN / 4, 256>>>(p_h1, p_h0);
    k_spmm<<<NN / 4, 256>>>(p_h0, p_h1);
    k_spmm<<<NN / 4, 256>>>(p_h1, p_h0);

    // GEMM2 + tanh -> h1
    k_gemm128<true><<<g1, 256>>>(p_h0, w_conv, b_conv, p_h1, NN);

    // GEMM3 (logits) -> d_out
    dim3 g3((NN + 127) / 128, 1);
    k_gemm<false><<<g3, 256>>>(p_h1, w_out, b_out, out, NN, 64);
}

// round 15
// speedup vs baseline: 1.0899x; 1.0899x over previous
#include <cuda_runtime.h>
#include <math.h>

typedef unsigned int u32;

#define NN 100000
#define D 256
#define DOUT 64
#define EMAX 3200000
#define SCAN_B 1024
#define NSCAN ((NN + SCAN_B - 1) / SCAN_B)

// ---------------- scratch (device globals; no allocation allowed) ----------
__device__ __align__(16) float g_h0[(size_t)NN * D];
__device__ __align__(16) float g_h1[(size_t)NN * D];
__device__ __align__(16) float g_w2[D * D];
__device__ float g_b2[D];
__device__ float g_sum[D], g_sumsq[D], g_a[D], g_bv[D];
__device__ int g_tick;
__device__ int g_cnt[NN], g_cur[NN];
__device__ int g_off[NN + 1];
__device__ int g_bsum[NSCAN], g_bpre[NSCAN];
__device__ int g_ecol[EMAX];
__device__ float g_eval[EMAX];

// ---------------- cp.async helpers ------------------------------------------
__device__ __forceinline__ void cp16(u32 s, const void* g) {
    asm volatile("cp.async.ca.shared.global [%0], [%1], 16;\n" :: "r"(s), "l"(g));
}
__device__ __forceinline__ void cp_commit() {
    asm volatile("cp.async.commit_group;\n");
}
__device__ __forceinline__ void cp_wait0() {
    asm volatile("cp.async.wait_group 0;\n");
}

// ---------------- zero scratch ----------------------------------------------
__global__ void k_zero() {
    int i = blockIdx.x * blockDim.x + threadIdx.x;
    if (i < NN) { g_cnt[i] = 0; g_cur[i] = 0; }
    if (i < D)  { g_sum[i] = 0.f; g_sumsq[i] = 0.f; }
    if (i == 0) g_tick = 0;
}

// ---------------- BatchNorm stats + last-block finalize ----------------------
__global__ void k_bnsumfin(const float* __restrict__ x,
                           const float* __restrict__ gamma,
                           const float* __restrict__ beta) {
    int c = threadIdx.x;
    int rows_per = (NN + gridDim.x - 1) / gridDim.x;
    int r0 = blockIdx.x * rows_per;
    int r1 = min(r0 + rows_per, NN);
    float s = 0.f, s2 = 0.f;
    for (int r = r0; r < r1; r++) {
        float v = x[(size_t)r * D + c];
        s += v; s2 += v * v;
    }
    atomicAdd(&g_sum[c], s);
    atomicAdd(&g_sumsq[c], s2);
    __threadfence();
    __shared__ int last;
    if (c == 0) last = (atomicAdd(&g_tick, 1) == (int)gridDim.x - 1);
    __syncthreads();
    if (last) {
        float mean = g_sum[c] * (1.f / NN);
        float var  = g_sumsq[c] * (1.f / NN) - mean * mean;
        float a = gamma[c] * rsqrtf(var + 1e-5f);
        g_a[c] = a;
        g_bv[c] = beta[c] - mean * a;
    }
}

// fused: blocks 0..255 -> w2[k][j] = a[k]*w_in[k][j]; block 256 -> b2
__global__ void k_prepwb(const float* __restrict__ w_in, const float* __restrict__ b_in) {
    int j = threadIdx.x;
    if (blockIdx.x < 256) {
        int k = blockIdx.x;
        g_w2[k * D + j] = g_a[k] * w_in[k * D + j];
    } else {
        float s = b_in[j];
        for (int k = 0; k < D; k++) s += g_bv[k] * w_in[k * D + j];
        g_b2[j] = s;
    }
}

// ---------------- CSR build --------------------------------------------------
__global__ void k_hist(const int* __restrict__ rows, int E) {
    int i = blockIdx.x * blockDim.x + threadIdx.x;
    if (i < E) atomicAdd(&g_cnt[rows[i]], 1);
}

__global__ void k_scan1() {
    __shared__ int s[SCAN_B];
    int t = threadIdx.x;
    int i = blockIdx.x * SCAN_B + t;
    int v = (i < NN) ? g_cnt[i] : 0;
    s[t] = v;
    __syncthreads();
    for (int o = 1; o < SCAN_B; o <<= 1) {
        int add = (t >= o) ? s[t - o] : 0;
        __syncthreads();
        s[t] += add;
        __syncthreads();
    }
    if (i < NN) g_off[i + 1] = s[t];
    if (t == SCAN_B - 1) g_bsum[blockIdx.x] = s[t];
}

__global__ void k_scan2(int nb) {
    if (threadIdx.x == 0) {
        int run = 0;
        for (int b = 0; b < nb; b++) { g_bpre[b] = run; run += g_bsum[b]; }
    }
}

__global__ void k_scan3() {
    int i = blockIdx.x * blockDim.x + threadIdx.x;
    if (i == 0) g_off[0] = 0;
    if (i < NN) g_off[i + 1] += g_bpre[i >> 10];
}

__global__ void k_scatter(const int* __restrict__ rows, const int* __restrict__ cols,
                          const float* __restrict__ vals, int E) {
    int i = blockIdx.x * blockDim.x + threadIdx.x;
    if (i >= E) return;
    int r = rows[i];
    int p = g_off[r] + atomicAdd(&g_cur[r], 1);
    g_ecol[p] = cols[i];
    g_eval[p] = vals[i];
}

// ---------------- SpMM (CSR gather, 64 threads/row, float4 lanes) -----------
__global__ void __launch_bounds__(256) k_spmm(const float* __restrict__ xin_f,
                                              float* __restrict__ yout_f) {
    const float4* __restrict__ xin = (const float4*)xin_f;
    float4* __restrict__ yout      = (float4*)yout_f;
    int r = blockIdx.x * 4 + (threadIdx.x >> 6);
    int lane = threadIdx.x & 63;
    int e = g_off[r], e1 = g_off[r + 1];
    float4 acc = make_float4(0.f, 0.f, 0.f, 0.f);
    for (; e + 4 <= e1; e += 4) {
        int c0 = g_ecol[e], c1 = g_ecol[e + 1], c2 = g_ecol[e + 2], c3 = g_ecol[e + 3];
        float v0 = g_eval[e], v1 = g_eval[e + 1], v2 = g_eval[e + 2], v3 = g_eval[e + 3];
        float4 x0 = xin[(size_t)c0 * 64 + lane];
        float4 x1 = xin[(size_t)c1 * 64 + lane];
        float4 x2 = xin[(size_t)c2 * 64 + lane];
        float4 x3 = xin[(size_t)c3 * 64 + lane];
        acc.x = fmaf(v0, x0.x, acc.x); acc.y = fmaf(v0, x0.y, acc.y);
        acc.z = fmaf(v0, x0.z, acc.z); acc.w = fmaf(v0, x0.w, acc.w);
        acc.x = fmaf(v1, x1.x, acc.x); acc.y = fmaf(v1, x1.y, acc.y);
        acc.z = fmaf(v1, x1.z, acc.z); acc.w = fmaf(v1, x1.w, acc.w);
        acc.x = fmaf(v2, x2.x, acc.x); acc.y = fmaf(v2, x2.y, acc.y);
        acc.z = fmaf(v2, x2.z, acc.z); acc.w = fmaf(v2, x2.w, acc.w);
        acc.x = fmaf(v3, x3.x, acc.x); acc.y = fmaf(v3, x3.y, acc.y);
        acc.z = fmaf(v3, x3.z, acc.z); acc.w = fmaf(v3, x3.w, acc.w);
    }
    for (; e < e1; e++) {
        int c = g_ecol[e]; float v = g_eval[e];
        float4 xv = xin[(size_t)c * 64 + lane];
        acc.x = fmaf(v, xv.x, acc.x); acc.y = fmaf(v, xv.y, acc.y);
        acc.z = fmaf(v, xv.z, acc.z); acc.w = fmaf(v, xv.w, acc.w);
    }
    yout[(size_t)r * 64 + lane] = acc;
}

// ------ fp32 GEMM 128x128, 8x8/thread, KTILE=16, cp.async B, dbl-buffered ---
template <bool TANH>
__global__ void __launch_bounds__(256, 2) k_gemm128(const float* __restrict__ A,
                                                    const float* __restrict__ B,
                                                    const float* __restrict__ bias,
                                                    float* __restrict__ C, int M) {
    __shared__ float As[2][16 * 132];   // transposed, padded: As[b][k*132 + m]
    __shared__ float Bs[2][16 * 128];   // natural: Bs[b][k*128 + n]
    const int tid = threadIdx.x;
    const int tx = tid & 15, ty = tid >> 4;
    const int bm = blockIdx.x * 128;
    const int bn = blockIdx.y * 128;

    float acc[8][8];
#pragma unroll
    for (int i = 0; i < 8; i++)
#pragma unroll
        for (int j = 0; j < 8; j++) acc[i][j] = 0.f;

    const int ar = tid >> 1, aq = (tid & 1) * 8;   // A: row, k-offset (2 float4)
    const int bk = tid >> 4, bc = (tid & 15) * 8;  // B: k-row, col (2 float4)
    const int gr = bm + ar;
    const bool avalid = (gr < M);
    const float* Arow = A + (size_t)gr * 256;
    const float* Bptr = B + (size_t)bk * 256 + bn + bc;

    u32 sB0 = (u32)__cvta_generic_to_shared(&Bs[0][bk * 128 + bc]);
    u32 sB1 = (u32)__cvta_generic_to_shared(&Bs[1][bk * 128 + bc]);

    // prologue: tile 0
    cp16(sB0, Bptr);
    cp16(sB0 + 16, Bptr + 4);
    cp_commit();
    {
        float4 a0 = make_float4(0.f, 0.f, 0.f, 0.f), a1 = a0;
        if (avalid) {
            a0 = *(const float4*)(Arow + aq);
            a1 = *(const float4*)(Arow + aq + 4);
        }
        As[0][(aq + 0) * 132 + ar] = a0.x;
        As[0][(aq + 1) * 132 + ar] = a0.y;
        As[0][(aq + 2) * 132 + ar] = a0.z;
        As[0][(aq + 3) * 132 + ar] = a0.w;
        As[0][(aq + 4) * 132 + ar] = a1.x;
        As[0][(aq + 5) * 132 + ar] = a1.y;
        As[0][(aq + 6) * 132 + ar] = a1.z;
        As[0][(aq + 7) * 132 + ar] = a1.w;
    }
    cp_wait0();
    __syncthreads();

    for (int k0 = 0; k0 < 256; k0 += 16) {
        const int buf = (k0 >> 4) & 1;
        const bool has_next = (k0 + 16) < 256;
        float4 a0n = make_float4(0.f, 0.f, 0.f, 0.f), a1n = a0n;
        if (has_next) {
            u32 sBn = buf ? sB0 : sB1;
            const float* Bn = Bptr + (size_t)(k0 + 16) * 256;
            cp16(sBn, Bn);
            cp16(sBn + 16, Bn + 4);
            cp_commit();
            if (avalid) {
                a0n = *(const float4*)(Arow + k0 + 16 + aq);
                a1n = *(const float4*)(Arow + k0 + 16 + aq + 4);
            }
        }
#pragma unroll
        for (int k = 0; k < 16; k++) {
            float4 x0 = *(const float4*)&As[buf][k * 132 + ty * 8];
            float4 x1 = *(const float4*)&As[buf][k * 132 + ty * 8 + 4];
            float4 y0 = *(const float4*)&Bs[buf][k * 128 + tx * 8];
            float4 y1 = *(const float4*)&Bs[buf][k * 128 + tx * 8 + 4];
            float aa[8] = {x0.x, x0.y, x0.z, x0.w, x1.x, x1.y, x1.z, x1.w};
            float bb[8] = {y0.x, y0.y, y0.z, y0.w, y1.x, y1.y, y1.z, y1.w};
#pragma unroll
            for (int i = 0; i < 8; i++)
#pragma unroll
                for (int j = 0; j < 8; j++)
                    acc[i][j] = fmaf(aa[i], bb[j], acc[i][j]);
        }
        if (has_next) {
            const int nb = buf ^ 1;
            As[nb][(aq + 0) * 132 + ar] = a0n.x;
            As[nb][(aq + 1) * 132 + ar] = a0n.y;
            As[nb][(aq + 2) * 132 + ar] = a0n.z;
            As[nb][(aq + 3) * 132 + ar] = a0n.w;
            As[nb][(aq + 4) * 132 + ar] = a1n.x;
            As[nb][(aq + 5) * 132 + ar] = a1n.y;
            As[nb][(aq + 6) * 132 + ar] = a1n.z;
            As[nb][(aq + 7) * 132 + ar] = a1n.w;
            cp_wait0();
            __syncthreads();
        }
    }

    float4 bl = *(const float4*)(bias + bn + tx * 8);
    float4 bh = *(const float4*)(bias + bn + tx * 8 + 4);
    float bb8[8] = {bl.x, bl.y, bl.z, bl.w, bh.x, bh.y, bh.z, bh.w};
#pragma unroll
    for (int i = 0; i < 8; i++) {
        int grr = bm + ty * 8 + i;
        if (grr >= M) continue;
        float o[8];
#pragma unroll
        for (int j = 0; j < 8; j++) {
            o[j] = acc[i][j] + bb8[j];
            if (TANH) o[j] = tanhf(o[j]);
        }
        *(float4*)(C + (size_t)grr * 256 + bn + tx * 8) =
            make_float4(o[0], o[1], o[2], o[3]);
        *(float4*)(C + (size_t)grr * 256 + bn + tx * 8 + 4) =
            make_float4(o[4], o[5], o[6], o[7]);
    }
}

// ---------------- fp32 GEMM 128x64 (N=64 logits) -----------------------------
template <bool TANH>
__global__ void __launch_bounds__(256) k_gemm(const float* __restrict__ A,
                                              const float* __restrict__ B,
                                              const float* __restrict__ bias,
                                              float* __restrict__ C,
                                              int M, int N) {
    __shared__ float As[16][128];
    __shared__ float Bs[16][64];
    const int tid = threadIdx.x;
    const int tx = tid & 15, ty = tid >> 4;
    const int bm = blockIdx.x * 128;
    const int bn = blockIdx.y * 64;
    float acc[8][4];
#pragma unroll
    for (int i = 0; i < 8; i++)
#pragma unroll
        for (int j = 0; j < 4; j++) acc[i][j] = 0.f;

    for (int k0 = 0; k0 < 256; k0 += 16) {
#pragma unroll
        for (int q = 0; q < 2; q++) {
            int idx = tid * 2 + q;
            int row = idx >> 2, cg = idx & 3;
            int gr = bm + row;
            float4 v = make_float4(0.f, 0.f, 0.f, 0.f);
            if (gr < M) v = *(const float4*)(A + (size_t)gr * 256 + k0 + cg * 4);
            As[cg * 4 + 0][row] = v.x;
            As[cg * 4 + 1][row] = v.y;
            As[cg * 4 + 2][row] = v.z;
            As[cg * 4 + 3][row] = v.w;
        }
        {
            int row = tid >> 4, c4 = tid & 15;
            *(float4*)&Bs[row][c4 * 4] =
                *(const float4*)(B + (size_t)(k0 + row) * N + bn + c4 * 4);
        }
        __syncthreads();
#pragma unroll
        for (int k = 0; k < 16; k++) {
            float4 a0 = *(const float4*)&As[k][ty * 8];
            float4 a1 = *(const float4*)&As[k][ty * 8 + 4];
            float4 b0 = *(const float4*)&Bs[k][tx * 4];
            float av[8] = {a0.x, a0.y, a0.z, a0.w, a1.x, a1.y, a1.z, a1.w};
            float bv4[4] = {b0.x, b0.y, b0.z, b0.w};
#pragma unroll
            for (int i = 0; i < 8; i++)
#pragma unroll
                for (int j = 0; j < 4; j++)
                    acc[i][j] = fmaf(av[i], bv4[j], acc[i][j]);
        }
        __syncthreads();
    }

    float4 bb = *(const float4*)(bias + bn + tx * 4);
#pragma unroll
    for (int i = 0; i < 8; i++) {
        int gr = bm + ty * 8 + i;
        if (gr < M) {
            float4 o;
            o.x = acc[i][0] + bb.x;
            o.y = acc[i][1] + bb.y;
            o.z = acc[i][2] + bb.z;
            o.w = acc[i][3] + bb.w;
            if (TANH) {
                o.x = tanhf(o.x); o.y = tanhf(o.y);
                o.z = tanhf(o.z); o.w = tanhf(o.w);
            }
            *(float4*)(C + (size_t)gr * N + bn + tx * 4) = o;
        }
    }
}

// ---------------- launch -----------------------------------------------------
extern "C" void kernel_launch(void* const* d_in, const int* in_sizes, int n_in,
                              void* d_out, int out_size) {
    const float* x      = (const float*)d_in[0];
    const int*   erows  = (const int*)d_in[1];
    const int*   ecols  = (const int*)d_in[2];
    const float* evals  = (const float*)d_in[3];
    const float* gamma  = (const float*)d_in[4];
    const float* beta   = (const float*)d_in[5];
    const float* w_in   = (const float*)d_in[6];
    const float* b_in   = (const float*)d_in[7];
    const float* w_conv = (const float*)d_in[8];
    const float* b_conv = (const float*)d_in[9];
    const float* w_out  = (const float*)d_in[10];
    const float* b_out  = (const float*)d_in[11];
    const int E = in_sizes[1];
    float* out = (float*)d_out;

    float *p_h0, *p_h1, *p_w2, *p_b2;
    cudaGetSymbolAddress((void**)&p_h0, g_h0);
    cudaGetSymbolAddress((void**)&p_h1, g_h1);
    cudaGetSymbolAddress((void**)&p_w2, g_w2);
    cudaGetSymbolAddress((void**)&p_b2, g_b2);

    // side stream + events: created once on the first (uncaptured) call, reused
    // inside capture where only launches / record / wait are issued.
    static cudaStream_t s_csr = 0;
    static cudaEvent_t ev_fork = 0, ev_csr = 0;
    if (!s_csr) {
        cudaStreamCreateWithFlags(&s_csr, cudaStreamNonBlocking);
        cudaEventCreateWithFlags(&ev_fork, cudaEventDisableTiming);
        cudaEventCreateWithFlags(&ev_csr, cudaEventDisableTiming);
    }

    // main stream: zero everything, then fork
    k_zero<<<(NN + 255) / 256, 256>>>();
    cudaEventRecord(ev_fork, 0);
    cudaStreamWaitEvent(s_csr, ev_fork, 0);

    // branch B (side stream): CSR build — independent of BN/GEMM1
    k_hist<<<(E + 255) / 256, 256, 0, s_csr>>>(erows, E);
    k_scan1<<<NSCAN, SCAN_B, 0, s_csr>>>();
    k_scan2<<<1, 32, 0, s_csr>>>(NSCAN);
    k_scan3<<<(NN + 255) / 256, 256, 0, s_csr>>>();
    k_scatter<<<(E + 255) / 256, 256, 0, s_csr>>>(erows, ecols, evals, E);
    cudaEventRecord(ev_csr, s_csr);

    // branch A (main stream): BN stats -> folded weights -> GEMM1
    k_bnsumfin<<<512, 256>>>(x, gamma, beta);
    k_prepwb<<<257, 256>>>(w_in, b_in);
    dim3 g1((NN + 127) / 128, 2);
    k_gemm128<true><<<g1, 256>>>(x, p_w2, p_b2, p_h0, NN);

    // join: SpMM needs both h0 (A) and CSR (B)
    cudaStreamWaitEvent(0, ev_csr, 0);

    // 4 fp32 SpMM hops: h0 -> h1 -> h0 -> h1 -> h0
    k_spmm<<<NN / 4, 256>>>(p_h0, p_h1);
    k_spmm<<<NN / 4, 256>>>(p_h1, p_h0);
    k_spmm<<<NN / 4, 256>>>(p_h0, p_h1);
    k_spmm<<<NN / 4, 256>>>(p_h1, p_h0);

    // GEMM2 + tanh -> h1
    k_gemm128<true><<<g1, 256>>>(p_h0, w_conv, b_conv, p_h1, NN);

    // GEMM3 (logits) -> d_out
    dim3 g3((NN + 127) / 128, 1);
    k_gemm<false><<<g3, 256>>>(p_h1, w_out, b_out, out, NN, 64);
}

// round 16
// speedup vs baseline: 1.0970x; 1.0066x over previous
#include <cuda_runtime.h>
#include <math.h>

typedef unsigned int u32;

#define NN 100000
#define D 256
#define DOUT 64
#define EMAX 3200000
#define SCAN_B 1024
#define NSCAN ((NN + SCAN_B - 1) / SCAN_B)

// ---------------- scratch (device globals; no allocation allowed) ----------
__device__ __align__(16) float g_h0[(size_t)NN * D];
__device__ __align__(16) float g_h1[(size_t)NN * D];
__device__ __align__(16) float g_w2[D * D];
__device__ float g_b2[D];
__device__ float g_sum[D], g_sumsq[D], g_a[D], g_bv[D];
__device__ int g_tick;
__device__ int g_cnt[NN], g_cur[NN];
__device__ int g_off[NN + 1];
__device__ int g_bsum[NSCAN], g_bpre[NSCAN];
__device__ int g_ecol[EMAX];
__device__ float g_eval[EMAX];

// ---------------- cp.async helpers ------------------------------------------
__device__ __forceinline__ void cp16(u32 s, const void* g) {
    asm volatile("cp.async.ca.shared.global [%0], [%1], 16;\n" :: "r"(s), "l"(g));
}
__device__ __forceinline__ void cp_commit() {
    asm volatile("cp.async.commit_group;\n");
}
__device__ __forceinline__ void cp_wait0() {
    asm volatile("cp.async.wait_group 0;\n");
}

// ---------------- zero scratch ----------------------------------------------
__global__ void k_zero() {
    int i = blockIdx.x * blockDim.x + threadIdx.x;
    if (i < NN) { g_cnt[i] = 0; g_cur[i] = 0; }
    if (i < D)  { g_sum[i] = 0.f; g_sumsq[i] = 0.f; }
    if (i == 0) g_tick = 0;
}

// ---------------- BatchNorm stats + last-block finalize ----------------------
__global__ void k_bnsumfin(const float* __restrict__ x,
                           const float* __restrict__ gamma,
                           const float* __restrict__ beta) {
    int c = threadIdx.x;
    int rows_per = (NN + gridDim.x - 1) / gridDim.x;
    int r0 = blockIdx.x * rows_per;
    int r1 = min(r0 + rows_per, NN);
    float s = 0.f, s2 = 0.f;
    for (int r = r0; r < r1; r++) {
        float v = x[(size_t)r * D + c];
        s += v; s2 += v * v;
    }
    atomicAdd(&g_sum[c], s);
    atomicAdd(&g_sumsq[c], s2);
    __threadfence();
    __shared__ int last;
    if (c == 0) last = (atomicAdd(&g_tick, 1) == (int)gridDim.x - 1);
    __syncthreads();
    if (last) {
        float mean = g_sum[c] * (1.f / NN);
        float var  = g_sumsq[c] * (1.f / NN) - mean * mean;
        float a = gamma[c] * rsqrtf(var + 1e-5f);
        g_a[c] = a;
        g_bv[c] = beta[c] - mean * a;
    }
}

// fused: blocks 0..255 -> w2[k][j] = a[k]*w_in[k][j]; block 256 -> b2
__global__ void k_prepwb(const float* __restrict__ w_in, const float* __restrict__ b_in) {
    int j = threadIdx.x;
    if (blockIdx.x < 256) {
        int k = blockIdx.x;
        g_w2[k * D + j] = g_a[k] * w_in[k * D + j];
    } else {
        float s = b_in[j];
        for (int k = 0; k < D; k++) s += g_bv[k] * w_in[k * D + j];
        g_b2[j] = s;
    }
}

// ---------------- CSR build --------------------------------------------------
__global__ void k_hist(const int* __restrict__ rows, int E) {
    int i = blockIdx.x * blockDim.x + threadIdx.x;
    if (i < E) atomicAdd(&g_cnt[rows[i]], 1);
}

__global__ void k_scan1() {
    __shared__ int s[SCAN_B];
    int t = threadIdx.x;
    int i = blockIdx.x * SCAN_B + t;
    int v = (i < NN) ? g_cnt[i] : 0;
    s[t] = v;
    __syncthreads();
    for (int o = 1; o < SCAN_B; o <<= 1) {
        int add = (t >= o) ? s[t - o] : 0;
        __syncthreads();
        s[t] += add;
        __syncthreads();
    }
    if (i < NN) g_off[i + 1] = s[t];
    if (t == SCAN_B - 1) g_bsum[blockIdx.x] = s[t];
}

__global__ void k_scan2(int nb) {
    if (threadIdx.x == 0) {
        int run = 0;
        for (int b = 0; b < nb; b++) { g_bpre[b] = run; run += g_bsum[b]; }
    }
}

__global__ void k_scan3() {
    int i = blockIdx.x * blockDim.x + threadIdx.x;
    if (i == 0) g_off[0] = 0;
    if (i < NN) g_off[i + 1] += g_bpre[i >> 10];
}

__global__ void k_scatter(const int* __restrict__ rows, const int* __restrict__ cols,
                          const float* __restrict__ vals, int E) {
    int i = blockIdx.x * blockDim.x + threadIdx.x;
    if (i >= E) return;
    int r = rows[i];
    int p = g_off[r] + atomicAdd(&g_cur[r], 1);
    g_ecol[p] = cols[i];
    g_eval[p] = vals[i];
}

// ---------------- SpMM (CSR gather, 64 threads/row, float4 lanes) -----------
__global__ void __launch_bounds__(256) k_spmm(const float* __restrict__ xin_f,
                                              float* __restrict__ yout_f) {
    const float4* __restrict__ xin = (const float4*)xin_f;
    float4* __restrict__ yout      = (float4*)yout_f;
    int r = blockIdx.x * 4 + (threadIdx.x >> 6);
    int lane = threadIdx.x & 63;
    int e = g_off[r], e1 = g_off[r + 1];
    float4 acc = make_float4(0.f, 0.f, 0.f, 0.f);
    for (; e + 4 <= e1; e += 4) {
        int c0 = g_ecol[e], c1 = g_ecol[e + 1], c2 = g_ecol[e + 2], c3 = g_ecol[e + 3];
        float v0 = g_eval[e], v1 = g_eval[e + 1], v2 = g_eval[e + 2], v3 = g_eval[e + 3];
        float4 x0 = xin[(size_t)c0 * 64 + lane];
        float4 x1 = xin[(size_t)c1 * 64 + lane];
        float4 x2 = xin[(size_t)c2 * 64 + lane];
        float4 x3 = xin[(size_t)c3 * 64 + lane];
        acc.x = fmaf(v0, x0.x, acc.x); acc.y = fmaf(v0, x0.y, acc.y);
        acc.z = fmaf(v0, x0.z, acc.z); acc.w = fmaf(v0, x0.w, acc.w);
        acc.x = fmaf(v1, x1.x, acc.x); acc.y = fmaf(v1, x1.y, acc.y);
        acc.z = fmaf(v1, x1.z, acc.z); acc.w = fmaf(v1, x1.w, acc.w);
        acc.x = fmaf(v2, x2.x, acc.x); acc.y = fmaf(v2, x2.y, acc.y);
        acc.z = fmaf(v2, x2.z, acc.z); acc.w = fmaf(v2, x2.w, acc.w);
        acc.x = fmaf(v3, x3.x, acc.x); acc.y = fmaf(v3, x3.y, acc.y);
        acc.z = fmaf(v3, x3.z, acc.z); acc.w = fmaf(v3, x3.w, acc.w);
    }
    for (; e < e1; e++) {
        int c = g_ecol[e]; float v = g_eval[e];
        float4 xv = xin[(size_t)c * 64 + lane];
        acc.x = fmaf(v, xv.x, acc.x); acc.y = fmaf(v, xv.y, acc.y);
        acc.z = fmaf(v, xv.z, acc.z); acc.w = fmaf(v, xv.w, acc.w);
    }
    yout[(size_t)r * 64 + lane] = acc;
}

// ------ fp32 GEMM 128x128, 8x8/thread, KTILE=16, cp.async B, dbl-buffered ---
template <bool TANH>
__global__ void __launch_bounds__(256, 2) k_gemm128(const float* __restrict__ A,
                                                    const float* __restrict__ B,
                                                    const float* __restrict__ bias,
                                                    float* __restrict__ C, int M) {
    __shared__ float As[2][16 * 132];   // transposed, padded: As[b][k*132 + m]
    __shared__ float Bs[2][16 * 128];   // natural: Bs[b][k*128 + n]
    const int tid = threadIdx.x;
    const int tx = tid & 15, ty = tid >> 4;
    const int bm = blockIdx.x * 128;
    const int bn = blockIdx.y * 128;

    float acc[8][8];
#pragma unroll
    for (int i = 0; i < 8; i++)
#pragma unroll
        for (int j = 0; j < 8; j++) acc[i][j] = 0.f;

    const int ar = tid >> 1, aq = (tid & 1) * 8;   // A: row, k-offset (2 float4)
    const int bk = tid >> 4, bc = (tid & 15) * 8;  // B: k-row, col (2 float4)
    const int gr = bm + ar;
    const bool avalid = (gr < M);
    const float* Arow = A + (size_t)gr * 256;
    const float* Bptr = B + (size_t)bk * 256 + bn + bc;

    u32 sB0 = (u32)__cvta_generic_to_shared(&Bs[0][bk * 128 + bc]);
    u32 sB1 = (u32)__cvta_generic_to_shared(&Bs[1][bk * 128 + bc]);

    // prologue: tile 0
    cp16(sB0, Bptr);
    cp16(sB0 + 16, Bptr + 4);
    cp_commit();
    {
        float4 a0 = make_float4(0.f, 0.f, 0.f, 0.f), a1 = a0;
        if (avalid) {
            a0 = *(const float4*)(Arow + aq);
            a1 = *(const float4*)(Arow + aq + 4);
        }
        As[0][(aq + 0) * 132 + ar] = a0.x;
        As[0][(aq + 1) * 132 + ar] = a0.y;
        As[0][(aq + 2) * 132 + ar] = a0.z;
        As[0][(aq + 3) * 132 + ar] = a0.w;
        As[0][(aq + 4) * 132 + ar] = a1.x;
        As[0][(aq + 5) * 132 + ar] = a1.y;
        As[0][(aq + 6) * 132 + ar] = a1.z;
        As[0][(aq + 7) * 132 + ar] = a1.w;
    }
    cp_wait0();
    __syncthreads();

    for (int k0 = 0; k0 < 256; k0 += 16) {
        const int buf = (k0 >> 4) & 1;
        const bool has_next = (k0 + 16) < 256;
        float4 a0n = make_float4(0.f, 0.f, 0.f, 0.f), a1n = a0n;
        if (has_next) {
            u32 sBn = buf ? sB0 : sB1;
            const float* Bn = Bptr + (size_t)(k0 + 16) * 256;
            cp16(sBn, Bn);
            cp16(sBn + 16, Bn + 4);
            cp_commit();
            if (avalid) {
                a0n = *(const float4*)(Arow + k0 + 16 + aq);
                a1n = *(const float4*)(Arow + k0 + 16 + aq + 4);
            }
        }
#pragma unroll
        for (int k = 0; k < 16; k++) {
            float4 x0 = *(const float4*)&As[buf][k * 132 + ty * 8];
            float4 x1 = *(const float4*)&As[buf][k * 132 + ty * 8 + 4];
            float4 y0 = *(const float4*)&Bs[buf][k * 128 + tx * 8];
            float4 y1 = *(const float4*)&Bs[buf][k * 128 + tx * 8 + 4];
            float aa[8] = {x0.x, x0.y, x0.z, x0.w, x1.x, x1.y, x1.z, x1.w};
            float bb[8] = {y0.x, y0.y, y0.z, y0.w, y1.x, y1.y, y1.z, y1.w};
#pragma unroll
            for (int i = 0; i < 8; i++)
#pragma unroll
                for (int j = 0; j < 8; j++)
                    acc[i][j] = fmaf(aa[i], bb[j], acc[i][j]);
        }
        if (has_next) {
            const int nb = buf ^ 1;
            As[nb][(aq + 0) * 132 + ar] = a0n.x;
            As[nb][(aq + 1) * 132 + ar] = a0n.y;
            As[nb][(aq + 2) * 132 + ar] = a0n.z;
            As[nb][(aq + 3) * 132 + ar] = a0n.w;
            As[nb][(aq + 4) * 132 + ar] = a1n.x;
            As[nb][(aq + 5) * 132 + ar] = a1n.y;
            As[nb][(aq + 6) * 132 + ar] = a1n.z;
            As[nb][(aq + 7) * 132 + ar] = a1n.w;
            cp_wait0();
            __syncthreads();
        }
    }

    float4 bl = *(const float4*)(bias + bn + tx * 8);
    float4 bh = *(const float4*)(bias + bn + tx * 8 + 4);
    float bb8[8] = {bl.x, bl.y, bl.z, bl.w, bh.x, bh.y, bh.z, bh.w};
#pragma unroll
    for (int i = 0; i < 8; i++) {
        int grr = bm + ty * 8 + i;
        if (grr >= M) continue;
        float o[8];
#pragma unroll
        for (int j = 0; j < 8; j++) {
            o[j] = acc[i][j] + bb8[j];
            if (TANH) o[j] = tanhf(o[j]);
        }
        *(float4*)(C + (size_t)grr * 256 + bn + tx * 8) =
            make_float4(o[0], o[1], o[2], o[3]);
        *(float4*)(C + (size_t)grr * 256 + bn + tx * 8 + 4) =
            make_float4(o[4], o[5], o[6], o[7]);
    }
}

// ------ fp32 GEMM 128x64 logits, KTILE=16, cp.async B, dbl-buffered ---------
// Same pipeline structure as k_gemm128, specialized to N=64 (w_out [256][64]).
__global__ void __launch_bounds__(256, 2) k_gemm64(const float* __restrict__ A,
                                                   const float* __restrict__ B,
                                                   const float* __restrict__ bias,
                                                   float* __restrict__ C, int M) {
    __shared__ float As[2][16 * 132];   // transposed, padded
    __shared__ float Bs[2][16 * 64];    // natural: Bs[b][k*64 + n]
    const int tid = threadIdx.x;
    const int tx = tid & 15, ty = tid >> 4;   // 16 x 16; 4 cols x 8 rows each
    const int bm = blockIdx.x * 128;

    float acc[8][4];
#pragma unroll
    for (int i = 0; i < 8; i++)
#pragma unroll
        for (int j = 0; j < 4; j++) acc[i][j] = 0.f;

    const int ar = tid >> 1, aq = (tid & 1) * 8;   // A: row, k-offset (2 float4)
    const int bk = tid >> 4, bc = (tid & 15) * 4;  // B: k-row, col (1 cp16)
    const int gr = bm + ar;
    const bool avalid = (gr < M);
    const float* Arow = A + (size_t)gr * 256;
    const float* Bptr = B + (size_t)bk * 64 + bc;

    u32 sB0 = (u32)__cvta_generic_to_shared(&Bs[0][bk * 64 + bc]);
    u32 sB1 = (u32)__cvta_generic_to_shared(&Bs[1][bk * 64 + bc]);

    // prologue: tile 0
    cp16(sB0, Bptr);
    cp_commit();
    {
        float4 a0 = make_float4(0.f, 0.f, 0.f, 0.f), a1 = a0;
        if (avalid) {
            a0 = *(const float4*)(Arow + aq);
            a1 = *(const float4*)(Arow + aq + 4);
        }
        As[0][(aq + 0) * 132 + ar] = a0.x;
        As[0][(aq + 1) * 132 + ar] = a0.y;
        As[0][(aq + 2) * 132 + ar] = a0.z;
        As[0][(aq + 3) * 132 + ar] = a0.w;
        As[0][(aq + 4) * 132 + ar] = a1.x;
        As[0][(aq + 5) * 132 + ar] = a1.y;
        As[0][(aq + 6) * 132 + ar] = a1.z;
        As[0][(aq + 7) * 132 + ar] = a1.w;
    }
    cp_wait0();
    __syncthreads();

    for (int k0 = 0; k0 < 256; k0 += 16) {
        const int buf = (k0 >> 4) & 1;
        const bool has_next = (k0 + 16) < 256;
        float4 a0n = make_float4(0.f, 0.f, 0.f, 0.f), a1n = a0n;
        if (has_next) {
            u32 sBn = buf ? sB0 : sB1;
            const float* Bn = Bptr + (size_t)(k0 + 16) * 64;
            cp16(sBn, Bn);
            cp_commit();
            if (avalid) {
                a0n = *(const float4*)(Arow + k0 + 16 + aq);
                a1n = *(const float4*)(Arow + k0 + 16 + aq + 4);
            }
        }
#pragma unroll
        for (int k = 0; k < 16; k++) {
            float4 x0 = *(const float4*)&As[buf][k * 132 + ty * 8];
            float4 x1 = *(const float4*)&As[buf][k * 132 + ty * 8 + 4];
            float4 y0 = *(const float4*)&Bs[buf][k * 64 + tx * 4];
            float aa[8] = {x0.x, x0.y, x0.z, x0.w, x1.x, x1.y, x1.z, x1.w};
            float bb[4] = {y0.x, y0.y, y0.z, y0.w};
#pragma unroll
            for (int i = 0; i < 8; i++)
#pragma unroll
                for (int j = 0; j < 4; j++)
                    acc[i][j] = fmaf(aa[i], bb[j], acc[i][j]);
        }
        if (has_next) {
            const int nb = buf ^ 1;
            As[nb][(aq + 0) * 132 + ar] = a0n.x;
            As[nb][(aq + 1) * 132 + ar] = a0n.y;
            As[nb][(aq + 2) * 132 + ar] = a0n.z;
            As[nb][(aq + 3) * 132 + ar] = a0n.w;
            As[nb][(aq + 4) * 132 + ar] = a1n.x;
            As[nb][(aq + 5) * 132 + ar] = a1n.y;
            As[nb][(aq + 6) * 132 + ar] = a1n.z;
            As[nb][(aq + 7) * 132 + ar] = a1n.w;
            cp_wait0();
            __syncthreads();
        }
    }

    float4 bb4 = *(const float4*)(bias + tx * 4);
#pragma unroll
    for (int i = 0; i < 8; i++) {
        int grr = bm + ty * 8 + i;
        if (grr >= M) continue;
        float4 o;
        o.x = acc[i][0] + bb4.x;
        o.y = acc[i][1] + bb4.y;
        o.z = acc[i][2] + bb4.z;
        o.w = acc[i][3] + bb4.w;
        *(float4*)(C + (size_t)grr * 64 + tx * 4) = o;
    }
}

// ---------------- launch -----------------------------------------------------
extern "C" void kernel_launch(void* const* d_in, const int* in_sizes, int n_in,
                              void* d_out, int out_size) {
    const float* x      = (const float*)d_in[0];
    const int*   erows  = (const int*)d_in[1];
    const int*   ecols  = (const int*)d_in[2];
    const float* evals  = (const float*)d_in[3];
    const float* gamma  = (const float*)d_in[4];
    const float* beta   = (const float*)d_in[5];
    const float* w_in   = (const float*)d_in[6];
    const float* b_in   = (const float*)d_in[7];
    const float* w_conv = (const float*)d_in[8];
    const float* b_conv = (const float*)d_in[9];
    const float* w_out  = (const float*)d_in[10];
    const float* b_out  = (const float*)d_in[11];
    const int E = in_sizes[1];
    float* out = (float*)d_out;

    float *p_h0, *p_h1, *p_w2, *p_b2;
    cudaGetSymbolAddress((void**)&p_h0, g_h0);
    cudaGetSymbolAddress((void**)&p_h1, g_h1);
    cudaGetSymbolAddress((void**)&p_w2, g_w2);
    cudaGetSymbolAddress((void**)&p_b2, g_b2);

    // side stream + events: created once on the first (uncaptured) call, reused
    // inside capture where only launches / record / wait are issued.
    static cudaStream_t s_csr = 0;
    static cudaEvent_t ev_fork = 0, ev_csr = 0;
    if (!s_csr) {
        cudaStreamCreateWithFlags(&s_csr, cudaStreamNonBlocking);
        cudaEventCreateWithFlags(&ev_fork, cudaEventDisableTiming);
        cudaEventCreateWithFlags(&ev_csr, cudaEventDisableTiming);
    }

    // main stream: zero everything, then fork
    k_zero<<<(NN + 255) / 256, 256>>>();
    cudaEventRecord(ev_fork, 0);
    cudaStreamWaitEvent(s_csr, ev_fork, 0);

    // branch B (side stream): CSR build — independent of BN/GEMM1
    k_hist<<<(E + 255) / 256, 256, 0, s_csr>>>(erows, E);
    k_scan1<<<NSCAN, SCAN_B, 0, s_csr>>>();
    k_scan2<<<1, 32, 0, s_csr>>>(NSCAN);
    k_scan3<<<(NN + 255) / 256, 256, 0, s_csr>>>();
    k_scatter<<<(E + 255) / 256, 256, 0, s_csr>>>(erows, ecols, evals, E);
    cudaEventRecord(ev_csr, s_csr);

    // branch A (main stream): BN stats -> folded weights -> GEMM1
    k_bnsumfin<<<512, 256>>>(x, gamma, beta);
    k_prepwb<<<257, 256>>>(w_in, b_in);
    dim3 g1((NN + 127) / 128, 2);
    k_gemm128<true><<<g1, 256>>>(x, p_w2, p_b2, p_h0, NN);

    // join: SpMM needs both h0 (A) and CSR (B)
    cudaStreamWaitEvent(0, ev_csr, 0);

    // 4 fp32 SpMM hops: h0 -> h1 -> h0 -> h1 -> h0
    k_spmm<<<NN / 4, 256>>>(p_h0, p_h1);
    k_spmm<<<NN / 4, 256>>>(p_h1, p_h0);
    k_spmm<<<NN / 4, 256>>>(p_h0, p_h1);
    k_spmm<<<NN / 4, 256>>>(p_h1, p_h0);

    // GEMM2 + tanh -> h1
    k_gemm128<true><<<g1, 256>>>(p_h0, w_conv, b_conv, p_h1, NN);

    // GEMM3 (logits, pipelined) -> d_out
    k_gemm64<<<(NN + 127) / 128, 256>>>(p_h1, w_out, b_out, out, NN);
}